// round 15
// baseline (speedup 1.0000x reference)
#include <cuda_runtime.h>

// Problem constants (fixed by setup_inputs)
#define B_  8
#define C_  24
#define H_  320
#define W_  640
#define HW_ (H_ * W_)            // 204800
#define PLANE2_ (HW_ / 2)        // 102400 float2 groups per image plane
#define NPIX2_ (B_ * PLANE2_)    // 819200 total float2 groups
#define NBHW_ (B_ * HW_)         // pred element count / prob plane base

#define THREADS_ 128

__global__ __launch_bounds__(THREADS_)
void sparse_regression_idx24_kernel(const float* __restrict__ cost,
                                    const float* __restrict__ disp,
                                    float* __restrict__ out)
{
    int p = blockIdx.x * THREADS_ + threadIdx.x;
    if (p >= NPIX2_) return;

    int b = p / PLANE2_;
    int r = p - b * PLANE2_;                 // float2 index within plane
    int base2 = b * (C_ * PLANE2_) + r;      // < 19.7M, fits int

    const float2* cbase = reinterpret_cast<const float2*>(cost) + base2;

    // ---- single batch: all 24 cost loads issued before any consume ----
    float2 creg[C_];
    #pragma unroll
    for (int j = 0; j < C_; ++j) {
        creg[j] = __ldcs(cbase + j * PLANE2_);
    }

    // running top-2 (value, channel-index) per lane (2 lanes)
    float v0[2], v1[2];
    int   i0[2], i1[2];
    #pragma unroll
    for (int l = 0; l < 2; ++l) {
        v0[l] = -3.4e38f; i0[l] = 0;
        v1[l] = -3.4e38f; i1[l] = 0;
    }

    #pragma unroll
    for (int j = 0; j < C_; ++j) {
        float cv[2] = {creg[j].x, creg[j].y};
        #pragma unroll
        for (int l = 0; l < 2; ++l) {
            float v = cv[l];
            if (v > v0[l]) {
                v1[l] = v0[l]; i1[l] = i0[l];
                v0[l] = v;     i0[l] = j;
            } else if (v > v1[l]) {
                v1[l] = v;     i1[l] = j;
            }
        }
    }

    // ---- gather disparity at top-2 indices: 4 independent scalar loads ----
    int pix0 = 2 * base2;           // lane 0 element index
    int pix1 = 2 * base2 + 1;       // lane 1
    float g00 = disp[pix0 + i0[0] * HW_];
    float g01 = disp[pix0 + i1[0] * HW_];
    float g10 = disp[pix1 + i0[1] * HW_];
    float g11 = disp[pix1 + i1[1] * HW_];

    float gd0[2] = {g00, g10};
    float gd1[2] = {g01, g11};

    // 2-way softmax (v1 <= v0, so e in (0,1]) and weighted disparity
    float pred[2], pr0[2], pr1[2];
    #pragma unroll
    for (int l = 0; l < 2; ++l) {
        float e   = __expf(v1[l] - v0[l]);
        float inv = 1.0f / (1.0f + e);
        float p0  = inv;
        float p1  = e * inv;
        pr0[l] = p0;
        pr1[l] = p1;
        pred[l] = gd0[l] * p0 + gd1[l] * p1;
    }

    int po = b * PLANE2_ + r;   // in float2 units
    __stcs(reinterpret_cast<float2*>(out) + po, make_float2(pred[0], pred[1]));

    // prob [B, 2, H, W] after pred [B, H, W]  (float2 units)
    int q0 = (NBHW_ / 2) + (b * 2 + 0) * PLANE2_ + r;
    int q1 = (NBHW_ / 2) + (b * 2 + 1) * PLANE2_ + r;
    __stcs(reinterpret_cast<float2*>(out) + q0, make_float2(pr0[0], pr0[1]));
    __stcs(reinterpret_cast<float2*>(out) + q1, make_float2(pr1[0], pr1[1]));
}

extern "C" void kernel_launch(void* const* d_in, const int* in_sizes, int n_in,
                              void* d_out, int out_size)
{
    const float* cost = (const float*)d_in[0];
    const float* disp = (const float*)d_in[1];
    float* out = (float*)d_out;

    const int blocks = (NPIX2_ + THREADS_ - 1) / THREADS_;   // 6400
    sparse_regression_idx24_kernel<<<blocks, THREADS_>>>(cost, disp, out);
}

// round 16
// speedup vs baseline: 1.0037x; 1.0037x over previous
#include <cuda_runtime.h>

// Problem constants (fixed by setup_inputs)
#define B_  8
#define C_  24
#define H_  320
#define W_  640
#define HW_ (H_ * W_)            // 204800
#define PLANE2_ (HW_ / 2)        // 102400 float2 groups per image plane
#define NPIX2_ (B_ * PLANE2_)    // 819200 total float2 groups
#define NBHW_ (B_ * HW_)         // pred element count / prob plane base

#define THREADS_ 128

__global__ __launch_bounds__(THREADS_)
void sparse_regression_idx24_kernel(const float* __restrict__ cost,
                                    const float* __restrict__ disp,
                                    float* __restrict__ out)
{
    int p = blockIdx.x * THREADS_ + threadIdx.x;
    if (p >= NPIX2_) return;

    int b = p / PLANE2_;
    int r = p - b * PLANE2_;                 // float2 index within plane
    int base2 = b * (C_ * PLANE2_) + r;      // < 19.7M, fits int

    const float2* cbase = reinterpret_cast<const float2*>(cost) + base2;

    // ---- single batch: all 24 cost loads issued before any consume ----
    float2 creg[C_];
    #pragma unroll
    for (int j = 0; j < C_; ++j) {
        creg[j] = __ldcs(cbase + j * PLANE2_);
    }

    // running top-2 (value, channel-index) per lane (2 lanes)
    float v0[2], v1[2];
    int   i0[2], i1[2];
    #pragma unroll
    for (int l = 0; l < 2; ++l) {
        v0[l] = -3.4e38f; i0[l] = 0;
        v1[l] = -3.4e38f; i1[l] = 0;
    }

    #pragma unroll
    for (int j = 0; j < C_; ++j) {
        float cv[2] = {creg[j].x, creg[j].y};
        #pragma unroll
        for (int l = 0; l < 2; ++l) {
            float v = cv[l];
            if (v > v0[l]) {
                v1[l] = v0[l]; i1[l] = i0[l];
                v0[l] = v;     i0[l] = j;
            } else if (v > v1[l]) {
                v1[l] = v;     i1[l] = j;
            }
        }
    }

    // ---- gather disparity at top-2 indices: 4 independent scalar loads ----
    int pix0 = 2 * base2;           // lane 0 element index
    int pix1 = 2 * base2 + 1;       // lane 1
    float g00 = disp[pix0 + i0[0] * HW_];
    float g01 = disp[pix0 + i1[0] * HW_];
    float g10 = disp[pix1 + i0[1] * HW_];
    float g11 = disp[pix1 + i1[1] * HW_];

    float gd0[2] = {g00, g10};
    float gd1[2] = {g01, g11};

    // 2-way softmax (v1 <= v0, so e in (0,1]) and weighted disparity
    float pred[2], pr0[2], pr1[2];
    #pragma unroll
    for (int l = 0; l < 2; ++l) {
        float e   = __expf(v1[l] - v0[l]);
        float inv = 1.0f / (1.0f + e);
        float p0  = inv;
        float p1  = e * inv;
        pr0[l] = p0;
        pr1[l] = p1;
        pred[l] = gd0[l] * p0 + gd1[l] * p1;
    }

    int po = b * PLANE2_ + r;   // in float2 units
    __stcs(reinterpret_cast<float2*>(out) + po, make_float2(pred[0], pred[1]));

    // prob [B, 2, H, W] after pred [B, H, W]  (float2 units)
    int q0 = (NBHW_ / 2) + (b * 2 + 0) * PLANE2_ + r;
    int q1 = (NBHW_ / 2) + (b * 2 + 1) * PLANE2_ + r;
    __stcs(reinterpret_cast<float2*>(out) + q0, make_float2(pr0[0], pr0[1]));
    __stcs(reinterpret_cast<float2*>(out) + q1, make_float2(pr1[0], pr1[1]));
}

extern "C" void kernel_launch(void* const* d_in, const int* in_sizes, int n_in,
                              void* d_out, int out_size)
{
    const float* cost = (const float*)d_in[0];
    const float* disp = (const float*)d_in[1];
    float* out = (float*)d_out;

    const int blocks = (NPIX2_ + THREADS_ - 1) / THREADS_;   // 6400
    sparse_regression_idx24_kernel<<<blocks, THREADS_>>>(cost, disp, out);
}

// round 17
// speedup vs baseline: 1.0458x; 1.0419x over previous
#include <cuda_runtime.h>

// Problem constants (fixed by setup_inputs)
#define B_  8
#define C_  24
#define H_  320
#define W_  640
#define HW_ (H_ * W_)            // 204800
#define PLANE2_ (HW_ / 2)        // 102400 float2 groups per image plane
#define NPIX2_ (B_ * PLANE2_)    // 819200 total float2 groups
#define NBHW_ (B_ * HW_)         // pred element count / prob plane base

#define THREADS_ 256

__global__ __launch_bounds__(THREADS_)
void sparse_regression_idx24b_kernel(const float* __restrict__ cost,
                                     const float* __restrict__ disp,
                                     float* __restrict__ out)
{
    int p = blockIdx.x * THREADS_ + threadIdx.x;
    if (p >= NPIX2_) return;

    int b = p / PLANE2_;
    int r = p - b * PLANE2_;                 // float2 index within plane
    int base2 = b * (C_ * PLANE2_) + r;      // < 19.7M, fits int

    const float2* cbase = reinterpret_cast<const float2*>(cost) + base2;

    // ---- single batch: all 24 cost loads issued before any consume ----
    float2 creg[C_];
    #pragma unroll
    for (int j = 0; j < C_; ++j) {
        creg[j] = __ldcs(cbase + j * PLANE2_);
    }

    // running top-2 (value, channel-index) per lane (2 lanes)
    float v0[2], v1[2];
    int   i0[2], i1[2];
    #pragma unroll
    for (int l = 0; l < 2; ++l) {
        v0[l] = -3.4e38f; i0[l] = 0;
        v1[l] = -3.4e38f; i1[l] = 0;
    }

    #pragma unroll
    for (int j = 0; j < C_; ++j) {
        float cv[2] = {creg[j].x, creg[j].y};
        #pragma unroll
        for (int l = 0; l < 2; ++l) {
            float v = cv[l];
            if (v > v0[l]) {
                v1[l] = v0[l]; i1[l] = i0[l];
                v0[l] = v;     i0[l] = j;
            } else if (v > v1[l]) {
                v1[l] = v;     i1[l] = j;
            }
        }
    }

    // ---- gather disparity at top-2 indices: 4 independent scalar loads ----
    int pix0 = 2 * base2;           // lane 0 element index
    int pix1 = 2 * base2 + 1;       // lane 1
    float g00 = __ldcs(disp + pix0 + i0[0] * HW_);
    float g01 = __ldcs(disp + pix0 + i1[0] * HW_);
    float g10 = __ldcs(disp + pix1 + i0[1] * HW_);
    float g11 = __ldcs(disp + pix1 + i1[1] * HW_);

    float gd0[2] = {g00, g10};
    float gd1[2] = {g01, g11};

    // 2-way softmax (v1 <= v0, so e in (0,1]) and weighted disparity
    float pred[2], pr0[2], pr1[2];
    #pragma unroll
    for (int l = 0; l < 2; ++l) {
        float e   = __expf(v1[l] - v0[l]);
        float inv = 1.0f / (1.0f + e);
        float p0  = inv;
        float p1  = e * inv;
        pr0[l] = p0;
        pr1[l] = p1;
        pred[l] = gd0[l] * p0 + gd1[l] * p1;
    }

    int po = b * PLANE2_ + r;   // in float2 units
    __stcs(reinterpret_cast<float2*>(out) + po, make_float2(pred[0], pred[1]));

    // prob [B, 2, H, W] after pred [B, H, W]  (float2 units)
    int q0 = (NBHW_ / 2) + (b * 2 + 0) * PLANE2_ + r;
    int q1 = (NBHW_ / 2) + (b * 2 + 1) * PLANE2_ + r;
    __stcs(reinterpret_cast<float2*>(out) + q0, make_float2(pr0[0], pr0[1]));
    __stcs(reinterpret_cast<float2*>(out) + q1, make_float2(pr1[0], pr1[1]));
}

extern "C" void kernel_launch(void* const* d_in, const int* in_sizes, int n_in,
                              void* d_out, int out_size)
{
    const float* cost = (const float*)d_in[0];
    const float* disp = (const float*)d_in[1];
    float* out = (float*)d_out;

    const int blocks = (NPIX2_ + THREADS_ - 1) / THREADS_;   // 3200
    sparse_regression_idx24b_kernel<<<blocks, THREADS_>>>(cost, disp, out);
}